// round 3
// baseline (speedup 1.0000x reference)
#include <cuda_runtime.h>

#define NJ 24
#define T  64      // bodies (=threads) per block
#define HJ 12      // joints per phase

__global__ __launch_bounds__(T, 7)
void fk_kernel(const float* __restrict__ pos,
               const float* __restrict__ rot,
               float* __restrict__ out, int nB)
{
    __shared__ float4 qs[HJ * T];    // 12*64*16 = 12288 B (double-used across phases)
    __shared__ float  ps[72 * T];    // 72*64*4  = 18432 B (pos in, globals out)

    const int t = threadIdx.x;
    const long long blockBase = (long long)blockIdx.x * T;
    const bool full = (blockBase + T <= nB);

    constexpr int PAR[NJ] = {-1,0,0,0,1,2,3,4,5,6,7,8,9,9,9,12,13,14,16,17,18,19,20,21};

    if (full) {
        const float4* qg = reinterpret_cast<const float4*>(rot) + blockBase * NJ;
        const float4* pg = reinterpret_cast<const float4*>(pos) + blockBase * 18;

        // ---- stage ALL positions + phase-0 quats (coalesced LDG.128 -> swizzled STS) ----
#pragma unroll
        for (int k = 0; k < 18; ++k) {
            int i4   = k * T + t;
            int body = i4 / 18;
            int kk   = i4 - body * 18;
            float4 v = pg[i4];
            int col  = body ^ kk;          // kk < 18
            int r0   = kk * 4;
            ps[(r0 + 0) * T + col] = v.x;
            ps[(r0 + 1) * T + col] = v.y;
            ps[(r0 + 2) * T + col] = v.z;
            ps[(r0 + 3) * T + col] = v.w;
        }
#pragma unroll
        for (int k = 0; k < HJ; ++k) {
            int i    = k * T + t;
            int body = i / HJ;
            int r    = i - body * HJ;      // phase-local joint row, 0..11
            qs[r * T + (body ^ r)] = qg[body * NJ + r];       // joints 0..11
        }
        __syncthreads();

        // ---- FK transforms; full unroll + constant indices -> registers ----
        float R[NJ][9];
        float G[NJ][3];

#pragma unroll
        for (int ph = 0; ph < 2; ++ph) {
            if (ph == 1) {
                __syncthreads();   // all phase-0 qs reads done
#pragma unroll
                for (int k = 0; k < HJ; ++k) {
                    int i    = k * T + t;
                    int body = i / HJ;
                    int r    = i - body * HJ;
                    qs[r * T + (body ^ r)] = qg[body * NJ + HJ + r];   // joints 12..23
                }
                __syncthreads();
            }
#pragma unroll
            for (int jr = 0; jr < HJ; ++jr) {
                const int j = ph * HJ + jr;
                float4 q = qs[jr * T + (t ^ jr)];
                float w = q.x, x = q.y, y = q.z, z = q.w;
                float s  = 2.0f / (w*w + x*x + y*y + z*z);   // == normalize-then-rotmat
                float xs = x*s, ys = y*s, zs = z*s;
                float wx = w*xs, wy = w*ys, wz = w*zs;
                float xx = x*xs, xy = x*ys, xz = x*zs;
                float yy = y*ys, yz = y*zs, zz = z*zs;

                float Rl[9] = {1.0f-(yy+zz), xy-wz,        xz+wy,
                               xy+wz,        1.0f-(xx+zz), yz-wx,
                               xz-wy,        yz+wx,        1.0f-(xx+yy)};

                const int r0 = 3*j+0, r1 = 3*j+1, r2 = 3*j+2;
                float t0 = ps[r0 * T + (t ^ (r0 >> 2))];
                float t1 = ps[r1 * T + (t ^ (r1 >> 2))];
                float t2 = ps[r2 * T + (t ^ (r2 >> 2))];

                const int pa = PAR[j];
                if (pa < 0) {
#pragma unroll
                    for (int k = 0; k < 9; ++k) R[j][k] = Rl[k];
                    G[j][0] = t0; G[j][1] = t1; G[j][2] = t2;
                } else {
#pragma unroll
                    for (int r = 0; r < 3; ++r)
#pragma unroll
                        for (int c = 0; c < 3; ++c)
                            R[j][r*3+c] = R[pa][r*3+0]*Rl[0*3+c]
                                        + R[pa][r*3+1]*Rl[1*3+c]
                                        + R[pa][r*3+2]*Rl[2*3+c];
                    G[j][0] = R[pa][0]*t0 + R[pa][1]*t1 + R[pa][2]*t2 + G[pa][0];
                    G[j][1] = R[pa][3]*t0 + R[pa][4]*t1 + R[pa][5]*t2 + G[pa][1];
                    G[j][2] = R[pa][6]*t0 + R[pa][7]*t1 + R[pa][8]*t2 + G[pa][2];
                }
                // write result into this thread's exclusive ps slots (no hazard)
                ps[r0 * T + (t ^ (r0 >> 2))] = G[j][0];
                ps[r1 * T + (t ^ (r1 >> 2))] = G[j][1];
                ps[r2 * T + (t ^ (r2 >> 2))] = G[j][2];
            }
        }
        __syncthreads();

        // ---- writeout: swizzled LDS -> coalesced STG.128 ----
        float4* og = reinterpret_cast<float4*>(out) + blockBase * 18;
#pragma unroll
        for (int k = 0; k < 18; ++k) {
            int i4   = k * T + t;
            int body = i4 / 18;
            int kk   = i4 - body * 18;
            int col  = body ^ kk;
            int r0   = kk * 4;
            float4 v;
            v.x = ps[(r0 + 0) * T + col];
            v.y = ps[(r0 + 1) * T + col];
            v.z = ps[(r0 + 2) * T + col];
            v.w = ps[(r0 + 3) * T + col];
            og[i4] = v;
        }
    } else {
        // ---- tail fallback (never taken: 131072 % 64 == 0) ----
        long long b = blockBase + t;
        if (b >= nB) return;
        const float4* q4 = reinterpret_cast<const float4*>(rot) + b * NJ;
        const float*  p  = pos + b * NJ * 3;
        float*        o  = out + b * NJ * 3;
        float R[NJ][9], G[NJ][3];
#pragma unroll
        for (int j = 0; j < NJ; ++j) {
            float4 q = q4[j];
            float w = q.x, x = q.y, y = q.z, z = q.w;
            float s  = 2.0f / (w*w + x*x + y*y + z*z);
            float xs = x*s, ys = y*s, zs = z*s;
            float wx = w*xs, wy = w*ys, wz = w*zs;
            float xx = x*xs, xy = x*ys, xz = x*zs;
            float yy = y*ys, yz = y*zs, zz = z*zs;
            float Rl[9] = {1.0f-(yy+zz), xy-wz, xz+wy,
                           xy+wz, 1.0f-(xx+zz), yz-wx,
                           xz-wy, yz+wx, 1.0f-(xx+yy)};
            float t0 = p[3*j+0], t1 = p[3*j+1], t2 = p[3*j+2];
            const int pa = PAR[j];
            if (pa < 0) {
#pragma unroll
                for (int k = 0; k < 9; ++k) R[j][k] = Rl[k];
                G[j][0] = t0; G[j][1] = t1; G[j][2] = t2;
            } else {
#pragma unroll
                for (int r = 0; r < 3; ++r)
#pragma unroll
                    for (int c = 0; c < 3; ++c)
                        R[j][r*3+c] = R[pa][r*3+0]*Rl[0*3+c]
                                    + R[pa][r*3+1]*Rl[1*3+c]
                                    + R[pa][r*3+2]*Rl[2*3+c];
                G[j][0] = R[pa][0]*t0 + R[pa][1]*t1 + R[pa][2]*t2 + G[pa][0];
                G[j][1] = R[pa][3]*t0 + R[pa][4]*t1 + R[pa][5]*t2 + G[pa][1];
                G[j][2] = R[pa][6]*t0 + R[pa][7]*t1 + R[pa][8]*t2 + G[pa][2];
            }
            o[3*j+0] = G[j][0]; o[3*j+1] = G[j][1]; o[3*j+2] = G[j][2];
        }
    }
}

extern "C" void kernel_launch(void* const* d_in, const int* in_sizes, int n_in,
                              void* d_out, int out_size)
{
    const float* pos = (const float*)d_in[1];
    const float* rot = (const float*)d_in[2];
    float* out = (float*)d_out;

    // allow the full shared-memory carveout so 7 blocks/SM fit
    static bool carveout_set = false;
    if (!carveout_set) {
        cudaFuncSetAttribute(fk_kernel, cudaFuncAttributePreferredSharedMemoryCarveout, 100);
        carveout_set = true;
    }

    int nB = in_sizes[1] / (NJ * 3);   // 131072
    int grid = (nB + T - 1) / T;
    fk_kernel<<<grid, T>>>(pos, rot, out, nB);
}

// round 4
// speedup vs baseline: 1.0324x; 1.0324x over previous
#include <cuda_runtime.h>

#define NJ  24
#define BB  32                // bodies per block
#define T   96                // threads per block (3 per body)

__global__ __launch_bounds__(T, 7)
void fk_kernel(const float* __restrict__ pos,
               const float* __restrict__ rot,
               float* __restrict__ out, int nB)
{
    __shared__ float4 qs [NJ * BB];   // 24*32*16 = 12288 B
    __shared__ float  pin[72 * BB];   //  9216 B  (local positions, read-only in compute)
    __shared__ float  pot[72 * BB];   //  9216 B  (global positions, write-only in compute)

    const int t = threadIdx.x;
    const long long blockBase = (long long)blockIdx.x * BB;
    const bool full = (blockBase + BB <= nB);

    constexpr int PAR[NJ] = {-1,0,0,0,1,2,3,4,5,6,7,8,9,9,9,12,13,14,16,17,18,19,20,21};

    if (full) {
        const float4* qg = reinterpret_cast<const float4*>(rot) + blockBase * NJ;
        const float4* pg = reinterpret_cast<const float4*>(pos) + blockBase * 18;

        // ---- stage quats: coalesced LDG.128 -> swizzled STS.128 (768 float4 / 96 thr) ----
#pragma unroll
        for (int k = 0; k < 8; ++k) {
            int i    = k * T + t;
            int body = i / NJ;
            int j    = i - body * NJ;
            qs[j * BB + (body ^ j)] = qg[i];
        }
        // ---- stage positions: coalesced LDG.128 -> swizzled scalar STS (576 float4) ----
#pragma unroll
        for (int k = 0; k < 6; ++k) {
            int i4   = k * T + t;
            int body = i4 / 18;
            int kk   = i4 - body * 18;
            float4 v = pg[i4];
            int col  = body ^ kk;
            int r0   = kk * 4;
            pin[(r0 + 0) * BB + col] = v.x;
            pin[(r0 + 1) * BB + col] = v.y;
            pin[(r0 + 2) * BB + col] = v.z;
            pin[(r0 + 3) * BB + col] = v.w;
        }
        __syncthreads();

        // ---- compute: 3 threads per body; thread r owns row r of every transform ----
        const int r = t % 3;          // row 0..2
        const int b = t / 3;          // body 0..31

        float Rr[NJ][3];              // row r of global rotation, per joint
        float Gr[NJ];                 // component r of global translation

#pragma unroll
        for (int j = 0; j < NJ; ++j) {
            float4 q = qs[j * BB + (b ^ j)];
            float w = q.x, x = q.y, y = q.z, z = q.w;
            float s  = 2.0f / (w*w + x*x + y*y + z*z);   // == normalize-then-rotmat
            float xs = x*s, ys = y*s, zs = z*s;
            float wx = w*xs, wy = w*ys, wz = w*zs;
            float xx = x*xs, xy = x*ys, xz = x*zs;
            float yy = y*ys, yz = y*zs, zz = z*zs;

            float Rl[9] = {1.0f-(yy+zz), xy-wz,        xz+wy,
                           xy+wz,        1.0f-(xx+zz), yz-wx,
                           xz-wy,        yz+wx,        1.0f-(xx+yy)};

            const int r0 = 3*j+0, r1 = 3*j+1, r2 = 3*j+2;
            float t0 = pin[r0 * BB + (b ^ (r0 >> 2))];
            float t1 = pin[r1 * BB + (b ^ (r1 >> 2))];
            float t2 = pin[r2 * BB + (b ^ (r2 >> 2))];

            const int pa = PAR[j];
            if (pa < 0) {
                Rr[j][0] = (r == 0) ? Rl[0] : (r == 1) ? Rl[3] : Rl[6];
                Rr[j][1] = (r == 0) ? Rl[1] : (r == 1) ? Rl[4] : Rl[7];
                Rr[j][2] = (r == 0) ? Rl[2] : (r == 1) ? Rl[5] : Rl[8];
                Gr[j]    = (r == 0) ? t0    : (r == 1) ? t1    : t2;
            } else {
#pragma unroll
                for (int c = 0; c < 3; ++c)
                    Rr[j][c] = Rr[pa][0]*Rl[0*3+c]
                             + Rr[pa][1]*Rl[1*3+c]
                             + Rr[pa][2]*Rl[2*3+c];
                Gr[j] = Rr[pa][0]*t0 + Rr[pa][1]*t1 + Rr[pa][2]*t2 + Gr[pa];
            }
            // row (3j+r) of this body's output, disjoint buffer -> no cross-warp race
            const int rw = 3*j + r;
            pot[rw * BB + (b ^ (rw >> 2))] = Gr[j];
        }
        __syncthreads();

        // ---- writeout: swizzled LDS -> coalesced STG.128 ----
        float4* og = reinterpret_cast<float4*>(out) + blockBase * 18;
#pragma unroll
        for (int k = 0; k < 6; ++k) {
            int i4   = k * T + t;
            int body = i4 / 18;
            int kk   = i4 - body * 18;
            int col  = body ^ kk;
            int r0   = kk * 4;
            float4 v;
            v.x = pot[(r0 + 0) * BB + col];
            v.y = pot[(r0 + 1) * BB + col];
            v.z = pot[(r0 + 2) * BB + col];
            v.w = pot[(r0 + 3) * BB + col];
            og[i4] = v;
        }
    } else {
        // ---- tail fallback (never taken: 131072 % 32 == 0): whole-body per thread ----
        long long b = blockBase + t;
        if (t >= BB || b >= nB) return;
        const float4* q4 = reinterpret_cast<const float4*>(rot) + b * NJ;
        const float*  p  = pos + b * NJ * 3;
        float*        o  = out + b * NJ * 3;
        float R[NJ][9], G[NJ][3];
#pragma unroll
        for (int j = 0; j < NJ; ++j) {
            float4 q = q4[j];
            float w = q.x, x = q.y, y = q.z, z = q.w;
            float s  = 2.0f / (w*w + x*x + y*y + z*z);
            float xs = x*s, ys = y*s, zs = z*s;
            float wx = w*xs, wy = w*ys, wz = w*zs;
            float xx = x*xs, xy = x*ys, xz = x*zs;
            float yy = y*ys, yz = y*zs, zz = z*zs;
            float Rl[9] = {1.0f-(yy+zz), xy-wz, xz+wy,
                           xy+wz, 1.0f-(xx+zz), yz-wx,
                           xz-wy, yz+wx, 1.0f-(xx+yy)};
            float t0 = p[3*j+0], t1 = p[3*j+1], t2 = p[3*j+2];
            const int pa = PAR[j];
            if (pa < 0) {
#pragma unroll
                for (int k = 0; k < 9; ++k) R[j][k] = Rl[k];
                G[j][0] = t0; G[j][1] = t1; G[j][2] = t2;
            } else {
#pragma unroll
                for (int rr = 0; rr < 3; ++rr)
#pragma unroll
                    for (int c = 0; c < 3; ++c)
                        R[j][rr*3+c] = R[pa][rr*3+0]*Rl[0*3+c]
                                     + R[pa][rr*3+1]*Rl[1*3+c]
                                     + R[pa][rr*3+2]*Rl[2*3+c];
                G[j][0] = R[pa][0]*t0 + R[pa][1]*t1 + R[pa][2]*t2 + G[pa][0];
                G[j][1] = R[pa][3]*t0 + R[pa][4]*t1 + R[pa][5]*t2 + G[pa][1];
                G[j][2] = R[pa][6]*t0 + R[pa][7]*t1 + R[pa][8]*t2 + G[pa][2];
            }
            o[3*j+0] = G[j][0]; o[3*j+1] = G[j][1]; o[3*j+2] = G[j][2];
        }
    }
}

extern "C" void kernel_launch(void* const* d_in, const int* in_sizes, int n_in,
                              void* d_out, int out_size)
{
    const float* pos = (const float*)d_in[1];
    const float* rot = (const float*)d_in[2];
    float* out = (float*)d_out;

    static bool carveout_set = false;
    if (!carveout_set) {
        cudaFuncSetAttribute(fk_kernel, cudaFuncAttributePreferredSharedMemoryCarveout, 100);
        carveout_set = true;
    }

    int nB = in_sizes[1] / (NJ * 3);   // 131072
    int grid = (nB + BB - 1) / BB;
    fk_kernel<<<grid, T>>>(pos, rot, out, nB);
}